// round 13
// baseline (speedup 1.0000x reference)
#include <cuda_runtime.h>
#include <cuda_bf16.h>
#include <cstdint>

// ============================================================================
// Problem: content[64,256], motion[64,512,128] -> M=32768 tokens
//   L1: [M,384]x[384,256]+b1, leaky(0.2)   (content half hoisted to CW bias)
//   L2: [M,256]x[256,512]+b2, leaky(0.2)
//   L3: [M,512]x[512,1152]+b3 -> out fp32
// Strategy: bf16x3 emulated-fp32 GEMM on mma.sync.m16n8k16.
// R13 = R12 tile body (unchanged) wrapped in ONE persistent fused kernel:
//   global atomic tile queue [L1 512 | L2 1024 | L3 2304], per-rowblock
//   completion counters gate L2/L3 tiles. Kills inter-layer launch drains
//   and tail-wave quantization. Laws: a16+b8 frags, 256 thr, 2 CTA/SM.
// ============================================================================

__device__ __nv_bfloat16 g_mhi[4194304];     // motion [32768,128]
__device__ __nv_bfloat16 g_mlo[4194304];
__device__ __nv_bfloat16 g_h1hi[8388608];    // [32768,256]
__device__ __nv_bfloat16 g_h1lo[8388608];
__device__ __nv_bfloat16 g_h2hi[16777216];   // [32768,512]
__device__ __nv_bfloat16 g_h2lo[16777216];
__device__ __nv_bfloat16 g_w1hi[32768],  g_w1lo[32768];    // W1m^T [256,128]
__device__ __nv_bfloat16 g_w2hi[131072], g_w2lo[131072];   // [512,256]
__device__ __nv_bfloat16 g_w3hi[589824], g_w3lo[589824];   // [1152,512]
__device__ float         g_cw[16384];        // CW [64,256] = content@W1c + b1
__device__ int           g_sync[513];        // [0]=qhead, [1..256]=cnt1, [257..512]=cnt2

// ---- helpers ----
__device__ __forceinline__ uint32_t smem_u32(const void* p) {
    uint32_t a;
    asm("{ .reg .u64 t; cvta.to.shared.u64 t, %1; cvt.u32.u64 %0, t; }"
        : "=r"(a) : "l"(p));
    return a;
}
__device__ __forceinline__ void cp16(uint32_t dst, const void* src) {
    asm volatile("cp.async.cg.shared.global [%0], [%1], 16;"
                 :: "r"(dst), "l"(src) : "memory");
}
#define CP_COMMIT() asm volatile("cp.async.commit_group;" ::: "memory")
#define CP_WAIT(n)  asm volatile("cp.async.wait_group %0;" :: "n"(n) : "memory")

__device__ __forceinline__ void ldsm4(uint32_t* r, uint32_t addr) {
    asm volatile("ldmatrix.sync.aligned.m8n8.x4.shared.b16 {%0,%1,%2,%3}, [%4];"
                 : "=r"(r[0]), "=r"(r[1]), "=r"(r[2]), "=r"(r[3]) : "r"(addr));
}
__device__ __forceinline__ void hmma(float* c, const uint32_t* a, const uint32_t* b) {
    asm volatile(
        "mma.sync.aligned.m16n8k16.row.col.f32.bf16.bf16.f32 "
        "{%0,%1,%2,%3}, {%4,%5,%6,%7}, {%8,%9}, {%0,%1,%2,%3};"
        : "+f"(c[0]), "+f"(c[1]), "+f"(c[2]), "+f"(c[3])
        : "r"(a[0]), "r"(a[1]), "r"(a[2]), "r"(a[3]), "r"(b[0]), "r"(b[1]));
}

// ============================================================================
// prep kernels (unchanged from R12)
// ============================================================================
__global__ void content_gemm(const float* __restrict__ content,
                             const float* __restrict__ W1,
                             const float* __restrict__ b1,
                             float* __restrict__ cw)
{
    __shared__ float crow[256];
    const int b = blockIdx.x;
    const int n = threadIdx.x;
    crow[n] = content[b * 256 + n];
    __syncthreads();
    float s = b1[n];
    #pragma unroll 8
    for (int k = 0; k < 256; ++k)
        s = fmaf(crow[k], W1[k * 256 + n], s);
    cw[b * 256 + n] = s;
}

__global__ void prep_motion(const float* __restrict__ motion,
                            __nv_bfloat16* __restrict__ hi,
                            __nv_bfloat16* __restrict__ lo)
{
    const int i = (blockIdx.x * 256 + threadIdx.x) * 4;
    const float4 v = *reinterpret_cast<const float4*>(motion + i);
    __nv_bfloat16 h0 = __float2bfloat16(v.x);
    __nv_bfloat16 h1 = __float2bfloat16(v.y);
    __nv_bfloat16 h2 = __float2bfloat16(v.z);
    __nv_bfloat16 h3 = __float2bfloat16(v.w);
    __nv_bfloat162 hv[2] = { __halves2bfloat162(h0, h1),
                             __halves2bfloat162(h2, h3) };
    __nv_bfloat162 lv[2] = {
        __halves2bfloat162(__float2bfloat16(v.x - __bfloat162float(h0)),
                           __float2bfloat16(v.y - __bfloat162float(h1))),
        __halves2bfloat162(__float2bfloat16(v.z - __bfloat162float(h2)),
                           __float2bfloat16(v.w - __bfloat162float(h3))) };
    *reinterpret_cast<uint2*>(hi + i) = *reinterpret_cast<uint2*>(hv);
    *reinterpret_cast<uint2*>(lo + i) = *reinterpret_cast<uint2*>(lv);
}

__global__ void prep_w(const float* __restrict__ W,
                       __nv_bfloat16* __restrict__ hi,
                       __nv_bfloat16* __restrict__ lo, int N, int K)
{
    __shared__ float t[32][33];
    const int nt = blockIdx.x * 32;
    const int kt = blockIdx.y * 32;
    const int tx = threadIdx.x;
    const int ty = threadIdx.y;
    #pragma unroll
    for (int i = 0; i < 32; i += 8)
        t[ty + i][tx] = W[(size_t)(kt + ty + i) * N + nt + tx];
    __syncthreads();
    #pragma unroll
    for (int i = 0; i < 32; i += 8) {
        const int n = nt + ty + i;
        const int k = kt + tx;
        const float v = t[tx][ty + i];
        const __nv_bfloat16 h = __float2bfloat16(v);
        hi[(size_t)n * K + k] = h;
        lo[(size_t)n * K + k] = __float2bfloat16(v - __bfloat162float(h));
    }
}

// ============================================================================
// tile body (identical math/structure to R12's gemm_hmma)
// ============================================================================
#define TILE_B 8192                  // 128 rows * 64 B
#define STG_B  (4 * TILE_B)          // 32768 B per stage
#define NSTG   3

template<int K, int NTOT, bool LEAKY, bool WRITE_F32, bool ROWBIAS>
__device__ __forceinline__ void tile_body(
    const __nv_bfloat16* __restrict__ Ahi,
    const __nv_bfloat16* __restrict__ Alo,
    const __nv_bfloat16* __restrict__ Bhi,
    const __nv_bfloat16* __restrict__ Blo,
    const float* __restrict__ bias,
    float* __restrict__ Cout,
    __nv_bfloat16* __restrict__ NxtHi,
    __nv_bfloat16* __restrict__ NxtLo,
    int rowBlock, int colBlock, uint32_t smem_base)
{
    constexpr int KC = K / 32;

    const int tid  = threadIdx.x;
    const int lane = tid & 31;
    const int wid  = tid >> 5;
    const int g    = lane >> 2;
    const int t2   = (lane & 3) * 2;
    const int wm   = (wid >> 2) * 64;
    const int wn   = (wid & 3) * 32;

    float acc[4][4][4];
    #pragma unroll
    for (int i = 0; i < 4; i++)
        #pragma unroll
        for (int j = 0; j < 4; j++)
            #pragma unroll
            for (int r = 0; r < 4; r++) acc[i][j][r] = 0.0f;

    const int aRowT = ((lane >> 3) & 1) * 8 + (lane & 7);
    const int aColT = (lane >> 4) * 8;
    const int bRowT = ((lane >> 4) & 1) * 8 + (lane & 7);
    const int bColT = ((lane >> 3) & 1) * 8;
    const int aswz = (aRowT >> 1) & 3;
    const int bswz = (bRowT >> 1) & 3;

    const int ldRow = tid >> 2;
    const int ldCh  = tid & 3;
    auto issue_chunk = [&](int c) {
        const int k0 = c * 32;
        const uint32_t sb = smem_base + (uint32_t)(c % NSTG) * STG_B;
        #pragma unroll
        for (int i = 0; i < 2; ++i) {
            const int r = ldRow + i * 64;
            const uint32_t off =
                (uint32_t)(r * 64 + ((ldCh ^ ((r >> 1) & 3)) * 16));
            const size_t ga = (size_t)(rowBlock + r) * K + k0 + ldCh * 8;
            const size_t gb = (size_t)(colBlock + r) * K + k0 + ldCh * 8;
            cp16(sb + off,                Ahi + ga);
            cp16(sb + TILE_B + off,       Alo + ga);
            cp16(sb + 2 * TILE_B + off,   Bhi + gb);
            cp16(sb + 3 * TILE_B + off,   Blo + gb);
        }
        CP_COMMIT();
    };

    issue_chunk(0);
    issue_chunk(1);

    for (int c = 0; c < KC; ++c) {
        if (c + 1 < KC) { CP_WAIT(1); }
        else            { CP_WAIT(0); }
        __syncthreads();
        if (c + 2 < KC) issue_chunk(c + 2);

        const uint32_t sb   = smem_base + (uint32_t)(c % NSTG) * STG_B;
        const uint32_t sAhi = sb;
        const uint32_t sAlo = sb + TILE_B;
        const uint32_t sBhi = sb + 2 * TILE_B;
        const uint32_t sBlo = sb + 3 * TILE_B;

        #pragma unroll
        for (int ks = 0; ks < 2; ++ks) {
            const int kb = ks * 16;
            uint32_t a[4][4], b[4][2];
            const uint32_t asg = (uint32_t)((((kb + aColT) >> 3) ^ aswz) * 16);
            const uint32_t bsg = (uint32_t)((((kb + bColT) >> 3) ^ bswz) * 16);
            const uint32_t aOff  = (uint32_t)((wm + aRowT) * 64) + asg;
            const uint32_t bOff0 = (uint32_t)((wn + bRowT) * 64) + bsg;
            const uint32_t bOff1 = (uint32_t)((wn + 16 + bRowT) * 64) + bsg;

            // ---- pass hl: Ahi * Blo ----
            #pragma unroll
            for (int mt = 0; mt < 4; ++mt)
                ldsm4(a[mt], sAhi + aOff + (uint32_t)(mt * 16 * 64));
            {
                uint32_t r4[4];
                ldsm4(r4, sBlo + bOff0);
                b[0][0] = r4[0]; b[0][1] = r4[1];
                b[1][0] = r4[2]; b[1][1] = r4[3];
                ldsm4(r4, sBlo + bOff1);
                b[2][0] = r4[0]; b[2][1] = r4[1];
                b[3][0] = r4[2]; b[3][1] = r4[3];
            }
            #pragma unroll
            for (int mt = 0; mt < 4; ++mt)
                #pragma unroll
                for (int nt = 0; nt < 4; ++nt)
                    hmma(acc[mt][nt], a[mt], b[nt]);

            // ---- pass hh: Ahi * Bhi ----
            {
                uint32_t r4[4];
                ldsm4(r4, sBhi + bOff0);
                b[0][0] = r4[0]; b[0][1] = r4[1];
                b[1][0] = r4[2]; b[1][1] = r4[3];
                ldsm4(r4, sBhi + bOff1);
                b[2][0] = r4[0]; b[2][1] = r4[1];
                b[3][0] = r4[2]; b[3][1] = r4[3];
            }
            #pragma unroll
            for (int mt = 0; mt < 4; ++mt)
                #pragma unroll
                for (int nt = 0; nt < 4; ++nt)
                    hmma(acc[mt][nt], a[mt], b[nt]);

            // ---- pass lh: Alo * Bhi ----
            #pragma unroll
            for (int mt = 0; mt < 4; ++mt)
                ldsm4(a[mt], sAlo + aOff + (uint32_t)(mt * 16 * 64));
            #pragma unroll
            for (int mt = 0; mt < 4; ++mt)
                #pragma unroll
                for (int nt = 0; nt < 4; ++nt)
                    hmma(acc[mt][nt], a[mt], b[nt]);
        }
    }

    __syncthreads();

    // ---- epilogue ----
    #pragma unroll
    for (int mt = 0; mt < 4; ++mt) {
        #pragma unroll
        for (int half = 0; half < 2; ++half) {
            const int grow = rowBlock + wm + mt * 16 + g + half * 8;
            const float* brow = ROWBIAS ? bias + (size_t)(grow >> 9) * NTOT
                                        : bias;
            #pragma unroll
            for (int nt = 0; nt < 4; ++nt) {
                const int gcol = colBlock + wn + nt * 8 + t2;
                float v0 = acc[mt][nt][half * 2 + 0] + brow[gcol];
                float v1 = acc[mt][nt][half * 2 + 1] + brow[gcol + 1];
                if (LEAKY) {
                    v0 = v0 >= 0.f ? v0 : 0.2f * v0;
                    v1 = v1 >= 0.f ? v1 : 0.2f * v1;
                }
                const size_t base = (size_t)grow * NTOT + gcol;
                if (WRITE_F32) {
                    float2 o; o.x = v0; o.y = v1;
                    *reinterpret_cast<float2*>(&Cout[base]) = o;
                } else {
                    __nv_bfloat16 h0 = __float2bfloat16(v0);
                    __nv_bfloat16 h1 = __float2bfloat16(v1);
                    __nv_bfloat16 l0 = __float2bfloat16(v0 - __bfloat162float(h0));
                    __nv_bfloat16 l1 = __float2bfloat16(v1 - __bfloat162float(h1));
                    *reinterpret_cast<__nv_bfloat162*>(&NxtHi[base]) =
                        __halves2bfloat162(h0, h1);
                    *reinterpret_cast<__nv_bfloat162*>(&NxtLo[base]) =
                        __halves2bfloat162(l0, l1);
                }
            }
        }
    }
}

// ============================================================================
// persistent fused kernel: atomic tile queue + rowblock dependency counters
//   tiles [0,512): L1 (rb=t>>1, cb=t&1)
//   tiles [512,1536): L2 (u=t-512: rb=u>>2, cb=u&3), needs cnt1[rb]==2
//   tiles [1536,3840): L3 (u=t-1536: rb=u/9, cb=u%9), needs cnt2[rb]==4
// ============================================================================
#define NTILES 3840

__global__ __launch_bounds__(256, 2)
void mlp_fused(const __nv_bfloat16* __restrict__ mhi,
               const __nv_bfloat16* __restrict__ mlo,
               const __nv_bfloat16* __restrict__ w1hi,
               const __nv_bfloat16* __restrict__ w1lo,
               const __nv_bfloat16* __restrict__ w2hi,
               const __nv_bfloat16* __restrict__ w2lo,
               const __nv_bfloat16* __restrict__ w3hi,
               const __nv_bfloat16* __restrict__ w3lo,
               const float* __restrict__ cw,
               const float* __restrict__ b2,
               const float* __restrict__ b3,
               __nv_bfloat16* __restrict__ h1hi,
               __nv_bfloat16* __restrict__ h1lo,
               __nv_bfloat16* __restrict__ h2hi,
               __nv_bfloat16* __restrict__ h2lo,
               float* __restrict__ out)
{
    extern __shared__ __nv_bfloat16 smem[];
    const uint32_t smem_base = smem_u32(smem);
    __shared__ int s_t;

    int* qhead = &g_sync[0];
    int* cnt1  = &g_sync[1];
    int* cnt2  = &g_sync[257];

    for (;;) {
        if (threadIdx.x == 0) s_t = atomicAdd(qhead, 1);
        __syncthreads();
        const int t = s_t;
        if (t >= NTILES) break;

        if (t < 512) {
            const int rb = t >> 1, cb = t & 1;
            tile_body<128, 256, true, false, true>(
                mhi, mlo, w1hi, w1lo, cw, nullptr, h1hi, h1lo,
                rb * 128, cb * 128, smem_base);
            __threadfence();
            __syncthreads();
            if (threadIdx.x == 0) atomicAdd(&cnt1[rb], 1);
        } else if (t < 1536) {
            const int u = t - 512;
            const int rb = u >> 2, cb = u & 3;
            if (threadIdx.x == 0)
                while (atomicAdd(&cnt1[rb], 0) < 2) __nanosleep(128);
            __syncthreads();
            tile_body<256, 512, true, false, false>(
                h1hi, h1lo, w2hi, w2lo, b2, nullptr, h2hi, h2lo,
                rb * 128, cb * 128, smem_base);
            __threadfence();
            __syncthreads();
            if (threadIdx.x == 0) atomicAdd(&cnt2[rb], 1);
        } else {
            const int u = t - 1536;
            const int rb = u / 9, cb = u - rb * 9;
            if (threadIdx.x == 0)
                while (atomicAdd(&cnt2[rb], 0) < 4) __nanosleep(128);
            __syncthreads();
            tile_body<512, 1152, false, true, false>(
                h2hi, h2lo, w3hi, w3lo, b3, out, nullptr, nullptr,
                rb * 128, cb * 128, smem_base);
        }
        __syncthreads();   // all threads done with s_t before next overwrite
    }
}

// ============================================================================
// launcher
// ============================================================================
extern "C" void kernel_launch(void* const* d_in, const int* in_sizes, int n_in,
                              void* d_out, int out_size)
{
    (void)in_sizes; (void)n_in; (void)out_size;
    const float* content = (const float*)d_in[0];
    const float* motion  = (const float*)d_in[1];
    const float* W1 = (const float*)d_in[2];
    const float* b1 = (const float*)d_in[3];
    const float* W2 = (const float*)d_in[4];
    const float* b2 = (const float*)d_in[5];
    const float* W3 = (const float*)d_in[6];
    const float* b3 = (const float*)d_in[7];
    float* out = (float*)d_out;

    __nv_bfloat16 *mhi, *mlo, *h1hi, *h1lo, *h2hi, *h2lo;
    __nv_bfloat16 *w1hi, *w1lo, *w2hi, *w2lo, *w3hi, *w3lo;
    float* cw;
    int* syncp;
    cudaGetSymbolAddress((void**)&mhi, g_mhi);
    cudaGetSymbolAddress((void**)&mlo, g_mlo);
    cudaGetSymbolAddress((void**)&h1hi, g_h1hi);
    cudaGetSymbolAddress((void**)&h1lo, g_h1lo);
    cudaGetSymbolAddress((void**)&h2hi, g_h2hi);
    cudaGetSymbolAddress((void**)&h2lo, g_h2lo);
    cudaGetSymbolAddress((void**)&w1hi, g_w1hi);
    cudaGetSymbolAddress((void**)&w1lo, g_w1lo);
    cudaGetSymbolAddress((void**)&w2hi, g_w2hi);
    cudaGetSymbolAddress((void**)&w2lo, g_w2lo);
    cudaGetSymbolAddress((void**)&w3hi, g_w3hi);
    cudaGetSymbolAddress((void**)&w3lo, g_w3lo);
    cudaGetSymbolAddress((void**)&cw, g_cw);
    cudaGetSymbolAddress((void**)&syncp, g_sync);

    const int SMEM = NSTG * STG_B;  // 98304 B
    cudaFuncSetAttribute((const void*)mlp_fused,
                         cudaFuncAttributeMaxDynamicSharedMemorySize, SMEM);

    int smc = 148;
    cudaDeviceGetAttribute(&smc, cudaDevAttrMultiProcessorCount, 0);
    const int grid = smc * 2;

    // ---- reset queue/counters (graph-capturable, replay-safe) ----
    cudaMemsetAsync(syncp, 0, sizeof(int) * 513);

    // ---- prep ----
    content_gemm<<<64, 256>>>(content, W1, b1, cw);
    prep_motion<<<4096, 256>>>(motion, mhi, mlo);
    prep_w<<<dim3(256 / 32, 128 / 32), dim3(32, 8)>>>(W1 + 256 * 256, w1hi, w1lo, 256, 128);
    prep_w<<<dim3(512 / 32, 256 / 32), dim3(32, 8)>>>(W2, w2hi, w2lo, 512, 256);
    prep_w<<<dim3(1152 / 32, 512 / 32), dim3(32, 8)>>>(W3, w3hi, w3lo, 1152, 512);

    // ---- fused persistent GEMM chain ----
    mlp_fused<<<grid, 256, SMEM>>>(mhi, mlo, w1hi, w1lo, w2hi, w2lo,
                                   w3hi, w3lo, cw, b2, b3,
                                   h1hi, h1lo, h2hi, h2lo, out);
}

// round 15
// speedup vs baseline: 1.5272x; 1.5272x over previous
#include <cuda_runtime.h>
#include <cuda_bf16.h>
#include <cstdint>

// ============================================================================
// Problem: content[64,256], motion[64,512,128] -> M=32768 tokens
//   L1: [M,384]x[384,256]+b1, leaky(0.2)   (content half hoisted to CW bias)
//   L2: [M,256]x[256,512]+b2, leaky(0.2)
//   L3: [M,512]x[512,1152]+b3 -> out fp32
// Strategy: bf16x3 emulated-fp32 GEMM on mma.sync.m16n8k16.
// R14 = R13 fused persistent kernel, with tile_body __noinline__ so each
//   instantiation gets its own register allocation (R13 inlined all three
//   -> union allocation -> acc spills -> 2x regression). Dependency polls
//   use volatile L2 reads instead of atomics.
// Laws: a16+b8 frags, 256 thr, 2 CTA/SM, NSTG=3.
// ============================================================================

__device__ __nv_bfloat16 g_mhi[4194304];     // motion [32768,128]
__device__ __nv_bfloat16 g_mlo[4194304];
__device__ __nv_bfloat16 g_h1hi[8388608];    // [32768,256]
__device__ __nv_bfloat16 g_h1lo[8388608];
__device__ __nv_bfloat16 g_h2hi[16777216];   // [32768,512]
__device__ __nv_bfloat16 g_h2lo[16777216];
__device__ __nv_bfloat16 g_w1hi[32768],  g_w1lo[32768];    // W1m^T [256,128]
__device__ __nv_bfloat16 g_w2hi[131072], g_w2lo[131072];   // [512,256]
__device__ __nv_bfloat16 g_w3hi[589824], g_w3lo[589824];   // [1152,512]
__device__ float         g_cw[16384];        // CW [64,256] = content@W1c + b1
__device__ int           g_sync[513];        // [0]=qhead, [1..256]=cnt1, [257..512]=cnt2

// ---- helpers ----
__device__ __forceinline__ uint32_t smem_u32(const void* p) {
    uint32_t a;
    asm("{ .reg .u64 t; cvta.to.shared.u64 t, %1; cvt.u32.u64 %0, t; }"
        : "=r"(a) : "l"(p));
    return a;
}
__device__ __forceinline__ void cp16(uint32_t dst, const void* src) {
    asm volatile("cp.async.cg.shared.global [%0], [%1], 16;"
                 :: "r"(dst), "l"(src) : "memory");
}
#define CP_COMMIT() asm volatile("cp.async.commit_group;" ::: "memory")
#define CP_WAIT(n)  asm volatile("cp.async.wait_group %0;" :: "n"(n) : "memory")

__device__ __forceinline__ void ldsm4(uint32_t* r, uint32_t addr) {
    asm volatile("ldmatrix.sync.aligned.m8n8.x4.shared.b16 {%0,%1,%2,%3}, [%4];"
                 : "=r"(r[0]), "=r"(r[1]), "=r"(r[2]), "=r"(r[3]) : "r"(addr));
}
__device__ __forceinline__ void hmma(float* c, const uint32_t* a, const uint32_t* b) {
    asm volatile(
        "mma.sync.aligned.m16n8k16.row.col.f32.bf16.bf16.f32 "
        "{%0,%1,%2,%3}, {%4,%5,%6,%7}, {%8,%9}, {%0,%1,%2,%3};"
        : "+f"(c[0]), "+f"(c[1]), "+f"(c[2]), "+f"(c[3])
        : "r"(a[0]), "r"(a[1]), "r"(a[2]), "r"(a[3]), "r"(b[0]), "r"(b[1]));
}
__device__ __forceinline__ int ld_cg(const int* p) {
    int v;
    asm volatile("ld.global.cg.b32 %0, [%1];" : "=r"(v) : "l"(p));
    return v;
}

// ============================================================================
// prep kernels (unchanged from R12)
// ============================================================================
__global__ void content_gemm(const float* __restrict__ content,
                             const float* __restrict__ W1,
                             const float* __restrict__ b1,
                             float* __restrict__ cw)
{
    __shared__ float crow[256];
    const int b = blockIdx.x;
    const int n = threadIdx.x;
    crow[n] = content[b * 256 + n];
    __syncthreads();
    float s = b1[n];
    #pragma unroll 8
    for (int k = 0; k < 256; ++k)
        s = fmaf(crow[k], W1[k * 256 + n], s);
    cw[b * 256 + n] = s;
}

__global__ void prep_motion(const float* __restrict__ motion,
                            __nv_bfloat16* __restrict__ hi,
                            __nv_bfloat16* __restrict__ lo)
{
    const int i = (blockIdx.x * 256 + threadIdx.x) * 4;
    const float4 v = *reinterpret_cast<const float4*>(motion + i);
    __nv_bfloat16 h0 = __float2bfloat16(v.x);
    __nv_bfloat16 h1 = __float2bfloat16(v.y);
    __nv_bfloat16 h2 = __float2bfloat16(v.z);
    __nv_bfloat16 h3 = __float2bfloat16(v.w);
    __nv_bfloat162 hv[2] = { __halves2bfloat162(h0, h1),
                             __halves2bfloat162(h2, h3) };
    __nv_bfloat162 lv[2] = {
        __halves2bfloat162(__float2bfloat16(v.x - __bfloat162float(h0)),
                           __float2bfloat16(v.y - __bfloat162float(h1))),
        __halves2bfloat162(__float2bfloat16(v.z - __bfloat162float(h2)),
                           __float2bfloat16(v.w - __bfloat162float(h3))) };
    *reinterpret_cast<uint2*>(hi + i) = *reinterpret_cast<uint2*>(hv);
    *reinterpret_cast<uint2*>(lo + i) = *reinterpret_cast<uint2*>(lv);
}

__global__ void prep_w(const float* __restrict__ W,
                       __nv_bfloat16* __restrict__ hi,
                       __nv_bfloat16* __restrict__ lo, int N, int K)
{
    __shared__ float t[32][33];
    const int nt = blockIdx.x * 32;
    const int kt = blockIdx.y * 32;
    const int tx = threadIdx.x;
    const int ty = threadIdx.y;
    #pragma unroll
    for (int i = 0; i < 32; i += 8)
        t[ty + i][tx] = W[(size_t)(kt + ty + i) * N + nt + tx];
    __syncthreads();
    #pragma unroll
    for (int i = 0; i < 32; i += 8) {
        const int n = nt + ty + i;
        const int k = kt + tx;
        const float v = t[tx][ty + i];
        const __nv_bfloat16 h = __float2bfloat16(v);
        hi[(size_t)n * K + k] = h;
        lo[(size_t)n * K + k] = __float2bfloat16(v - __bfloat162float(h));
    }
}

// ============================================================================
// tile body — __noinline__: each instantiation is a standalone ABI function
// with its OWN register allocation (prevents union-allocation spills).
// Math/structure identical to R12's gemm_hmma.
// ============================================================================
#define TILE_B 8192                  // 128 rows * 64 B
#define STG_B  (4 * TILE_B)          // 32768 B per stage
#define NSTG   3

template<int K, int NTOT, bool LEAKY, bool WRITE_F32, bool ROWBIAS>
__device__ __noinline__ void tile_body(
    const __nv_bfloat16* __restrict__ Ahi,
    const __nv_bfloat16* __restrict__ Alo,
    const __nv_bfloat16* __restrict__ Bhi,
    const __nv_bfloat16* __restrict__ Blo,
    const float* __restrict__ bias,
    float* __restrict__ Cout,
    __nv_bfloat16* __restrict__ NxtHi,
    __nv_bfloat16* __restrict__ NxtLo,
    int rowBlock, int colBlock, uint32_t smem_base)
{
    constexpr int KC = K / 32;

    const int tid  = threadIdx.x;
    const int lane = tid & 31;
    const int wid  = tid >> 5;
    const int g    = lane >> 2;
    const int t2   = (lane & 3) * 2;
    const int wm   = (wid >> 2) * 64;
    const int wn   = (wid & 3) * 32;

    float acc[4][4][4];
    #pragma unroll
    for (int i = 0; i < 4; i++)
        #pragma unroll
        for (int j = 0; j < 4; j++)
            #pragma unroll
            for (int r = 0; r < 4; r++) acc[i][j][r] = 0.0f;

    const int aRowT = ((lane >> 3) & 1) * 8 + (lane & 7);
    const int aColT = (lane >> 4) * 8;
    const int bRowT = ((lane >> 4) & 1) * 8 + (lane & 7);
    const int bColT = ((lane >> 3) & 1) * 8;
    const int aswz = (aRowT >> 1) & 3;
    const int bswz = (bRowT >> 1) & 3;

    const int ldRow = tid >> 2;
    const int ldCh  = tid & 3;
    auto issue_chunk = [&](int c) {
        const int k0 = c * 32;
        const uint32_t sb = smem_base + (uint32_t)(c % NSTG) * STG_B;
        #pragma unroll
        for (int i = 0; i < 2; ++i) {
            const int r = ldRow + i * 64;
            const uint32_t off =
                (uint32_t)(r * 64 + ((ldCh ^ ((r >> 1) & 3)) * 16));
            const size_t ga = (size_t)(rowBlock + r) * K + k0 + ldCh * 8;
            const size_t gb = (size_t)(colBlock + r) * K + k0 + ldCh * 8;
            cp16(sb + off,                Ahi + ga);
            cp16(sb + TILE_B + off,       Alo + ga);
            cp16(sb + 2 * TILE_B + off,   Bhi + gb);
            cp16(sb + 3 * TILE_B + off,   Blo + gb);
        }
        CP_COMMIT();
    };

    issue_chunk(0);
    issue_chunk(1);

    for (int c = 0; c < KC; ++c) {
        if (c + 1 < KC) { CP_WAIT(1); }
        else            { CP_WAIT(0); }
        __syncthreads();
        if (c + 2 < KC) issue_chunk(c + 2);

        const uint32_t sb   = smem_base + (uint32_t)(c % NSTG) * STG_B;
        const uint32_t sAhi = sb;
        const uint32_t sAlo = sb + TILE_B;
        const uint32_t sBhi = sb + 2 * TILE_B;
        const uint32_t sBlo = sb + 3 * TILE_B;

        #pragma unroll
        for (int ks = 0; ks < 2; ++ks) {
            const int kb = ks * 16;
            uint32_t a[4][4], b[4][2];
            const uint32_t asg = (uint32_t)((((kb + aColT) >> 3) ^ aswz) * 16);
            const uint32_t bsg = (uint32_t)((((kb + bColT) >> 3) ^ bswz) * 16);
            const uint32_t aOff  = (uint32_t)((wm + aRowT) * 64) + asg;
            const uint32_t bOff0 = (uint32_t)((wn + bRowT) * 64) + bsg;
            const uint32_t bOff1 = (uint32_t)((wn + 16 + bRowT) * 64) + bsg;

            // ---- pass hl: Ahi * Blo ----
            #pragma unroll
            for (int mt = 0; mt < 4; ++mt)
                ldsm4(a[mt], sAhi + aOff + (uint32_t)(mt * 16 * 64));
            {
                uint32_t r4[4];
                ldsm4(r4, sBlo + bOff0);
                b[0][0] = r4[0]; b[0][1] = r4[1];
                b[1][0] = r4[2]; b[1][1] = r4[3];
                ldsm4(r4, sBlo + bOff1);
                b[2][0] = r4[0]; b[2][1] = r4[1];
                b[3][0] = r4[2]; b[3][1] = r4[3];
            }
            #pragma unroll
            for (int mt = 0; mt < 4; ++mt)
                #pragma unroll
                for (int nt = 0; nt < 4; ++nt)
                    hmma(acc[mt][nt], a[mt], b[nt]);

            // ---- pass hh: Ahi * Bhi ----
            {
                uint32_t r4[4];
                ldsm4(r4, sBhi + bOff0);
                b[0][0] = r4[0]; b[0][1] = r4[1];
                b[1][0] = r4[2]; b[1][1] = r4[3];
                ldsm4(r4, sBhi + bOff1);
                b[2][0] = r4[0]; b[2][1] = r4[1];
                b[3][0] = r4[2]; b[3][1] = r4[3];
            }
            #pragma unroll
            for (int mt = 0; mt < 4; ++mt)
                #pragma unroll
                for (int nt = 0; nt < 4; ++nt)
                    hmma(acc[mt][nt], a[mt], b[nt]);

            // ---- pass lh: Alo * Bhi ----
            #pragma unroll
            for (int mt = 0; mt < 4; ++mt)
                ldsm4(a[mt], sAlo + aOff + (uint32_t)(mt * 16 * 64));
            #pragma unroll
            for (int mt = 0; mt < 4; ++mt)
                #pragma unroll
                for (int nt = 0; nt < 4; ++nt)
                    hmma(acc[mt][nt], a[mt], b[nt]);
        }
    }

    __syncthreads();

    // ---- epilogue ----
    #pragma unroll
    for (int mt = 0; mt < 4; ++mt) {
        #pragma unroll
        for (int half = 0; half < 2; ++half) {
            const int grow = rowBlock + wm + mt * 16 + g + half * 8;
            const float* brow = ROWBIAS ? bias + (size_t)(grow >> 9) * NTOT
                                        : bias;
            #pragma unroll
            for (int nt = 0; nt < 4; ++nt) {
                const int gcol = colBlock + wn + nt * 8 + t2;
                float v0 = acc[mt][nt][half * 2 + 0] + brow[gcol];
                float v1 = acc[mt][nt][half * 2 + 1] + brow[gcol + 1];
                if (LEAKY) {
                    v0 = v0 >= 0.f ? v0 : 0.2f * v0;
                    v1 = v1 >= 0.f ? v1 : 0.2f * v1;
                }
                const size_t base = (size_t)grow * NTOT + gcol;
                if (WRITE_F32) {
                    float2 o; o.x = v0; o.y = v1;
                    *reinterpret_cast<float2*>(&Cout[base]) = o;
                } else {
                    __nv_bfloat16 h0 = __float2bfloat16(v0);
                    __nv_bfloat16 h1 = __float2bfloat16(v1);
                    __nv_bfloat16 l0 = __float2bfloat16(v0 - __bfloat162float(h0));
                    __nv_bfloat16 l1 = __float2bfloat16(v1 - __bfloat162float(h1));
                    *reinterpret_cast<__nv_bfloat162*>(&NxtHi[base]) =
                        __halves2bfloat162(h0, h1);
                    *reinterpret_cast<__nv_bfloat162*>(&NxtLo[base]) =
                        __halves2bfloat162(l0, l1);
                }
            }
        }
    }
}

// ============================================================================
// persistent fused kernel: atomic tile queue + rowblock dependency counters
//   tiles [0,512): L1 (rb=t>>1, cb=t&1)
//   tiles [512,1536): L2 (u=t-512: rb=u>>2, cb=u&3), needs cnt1[rb]==2
//   tiles [1536,3840): L3 (u=t-1536: rb=u/9, cb=u%9), needs cnt2[rb]==4
// ============================================================================
#define NTILES 3840

__global__ __launch_bounds__(256, 2)
void mlp_fused(const __nv_bfloat16* __restrict__ mhi,
               const __nv_bfloat16* __restrict__ mlo,
               const __nv_bfloat16* __restrict__ w1hi,
               const __nv_bfloat16* __restrict__ w1lo,
               const __nv_bfloat16* __restrict__ w2hi,
               const __nv_bfloat16* __restrict__ w2lo,
               const __nv_bfloat16* __restrict__ w3hi,
               const __nv_bfloat16* __restrict__ w3lo,
               const float* __restrict__ cw,
               const float* __restrict__ b2,
               const float* __restrict__ b3,
               __nv_bfloat16* __restrict__ h1hi,
               __nv_bfloat16* __restrict__ h1lo,
               __nv_bfloat16* __restrict__ h2hi,
               __nv_bfloat16* __restrict__ h2lo,
               float* __restrict__ out)
{
    extern __shared__ __nv_bfloat16 smem[];
    const uint32_t smem_base = smem_u32(smem);
    __shared__ int s_t;

    int* qhead = &g_sync[0];
    int* cnt1  = &g_sync[1];
    int* cnt2  = &g_sync[257];

    for (;;) {
        if (threadIdx.x == 0) s_t = atomicAdd(qhead, 1);
        __syncthreads();
        const int t = s_t;
        if (t >= NTILES) break;

        if (t < 512) {
            const int rb = t >> 1, cb = t & 1;
            tile_body<128, 256, true, false, true>(
                mhi, mlo, w1hi, w1lo, cw, nullptr, h1hi, h1lo,
                rb * 128, cb * 128, smem_base);
            __threadfence();
            __syncthreads();
            if (threadIdx.x == 0) atomicAdd(&cnt1[rb], 1);
        } else if (t < 1536) {
            const int u = t - 512;
            const int rb = u >> 2, cb = u & 3;
            if (threadIdx.x == 0)
                while (ld_cg(&cnt1[rb]) < 2) __nanosleep(64);
            __syncthreads();
            tile_body<256, 512, true, false, false>(
                h1hi, h1lo, w2hi, w2lo, b2, nullptr, h2hi, h2lo,
                rb * 128, cb * 128, smem_base);
            __threadfence();
            __syncthreads();
            if (threadIdx.x == 0) atomicAdd(&cnt2[rb], 1);
        } else {
            const int u = t - 1536;
            const int rb = u / 9, cb = u - rb * 9;
            if (threadIdx.x == 0)
                while (ld_cg(&cnt2[rb]) < 4) __nanosleep(64);
            __syncthreads();
            tile_body<512, 1152, false, true, false>(
                h2hi, h2lo, w3hi, w3lo, b3, out, nullptr, nullptr,
                rb * 128, cb * 128, smem_base);
        }
        __syncthreads();   // all threads done with s_t before next overwrite
    }
}

// ============================================================================
// launcher
// ============================================================================
extern "C" void kernel_launch(void* const* d_in, const int* in_sizes, int n_in,
                              void* d_out, int out_size)
{
    (void)in_sizes; (void)n_in; (void)out_size;
    const float* content = (const float*)d_in[0];
    const float* motion  = (const float*)d_in[1];
    const float* W1 = (const float*)d_in[2];
    const float* b1 = (const float*)d_in[3];
    const float* W2 = (const float*)d_in[4];
    const float* b2 = (const float*)d_in[5];
    const float* W3 = (const float*)d_in[6];
    const float* b3 = (const float*)d_in[7];
    float* out = (float*)d_out;

    __nv_bfloat16 *mhi, *mlo, *h1hi, *h1lo, *h2hi, *h2lo;
    __nv_bfloat16 *w1hi, *w1lo, *w2hi, *w2lo, *w3hi, *w3lo;
    float* cw;
    int* syncp;
    cudaGetSymbolAddress((void**)&mhi, g_mhi);
    cudaGetSymbolAddress((void**)&mlo, g_mlo);
    cudaGetSymbolAddress((void**)&h1hi, g_h1hi);
    cudaGetSymbolAddress((void**)&h1lo, g_h1lo);
    cudaGetSymbolAddress((void**)&h2hi, g_h2hi);
    cudaGetSymbolAddress((void**)&h2lo, g_h2lo);
    cudaGetSymbolAddress((void**)&w1hi, g_w1hi);
    cudaGetSymbolAddress((void**)&w1lo, g_w1lo);
    cudaGetSymbolAddress((void**)&w2hi, g_w2hi);
    cudaGetSymbolAddress((void**)&w2lo, g_w2lo);
    cudaGetSymbolAddress((void**)&w3hi, g_w3hi);
    cudaGetSymbolAddress((void**)&w3lo, g_w3lo);
    cudaGetSymbolAddress((void**)&cw, g_cw);
    cudaGetSymbolAddress((void**)&syncp, g_sync);

    const int SMEM = NSTG * STG_B;  // 98304 B
    cudaFuncSetAttribute((const void*)mlp_fused,
                         cudaFuncAttributeMaxDynamicSharedMemorySize, SMEM);

    int smc = 148;
    cudaDeviceGetAttribute(&smc, cudaDevAttrMultiProcessorCount, 0);
    const int grid = smc * 2;

    // ---- reset queue/counters (graph-capturable, replay-safe) ----
    cudaMemsetAsync(syncp, 0, sizeof(int) * 513);

    // ---- prep ----
    content_gemm<<<64, 256>>>(content, W1, b1, cw);
    prep_motion<<<4096, 256>>>(motion, mhi, mlo);
    prep_w<<<dim3(256 / 32, 128 / 32), dim3(32, 8)>>>(W1 + 256 * 256, w1hi, w1lo, 256, 128);
    prep_w<<<dim3(512 / 32, 256 / 32), dim3(32, 8)>>>(W2, w2hi, w2lo, 512, 256);
    prep_w<<<dim3(1152 / 32, 512 / 32), dim3(32, 8)>>>(W3, w3hi, w3lo, 1152, 512);

    // ---- fused persistent GEMM chain ----
    mlp_fused<<<grid, 256, SMEM>>>(mhi, mlo, w1hi, w1lo, w2hi, w2lo,
                                   w3hi, w3lo, cw, b2, b3,
                                   h1hi, h1lo, h2hi, h2lo, out);
}